// round 3
// baseline (speedup 1.0000x reference)
#include <cuda_runtime.h>
#include <math.h>

#define Bn   2048
#define Hn   64
#define An   32
#define Sn   32
#define Dn   200
#define OUTC 296
#define BT   16
#define NT   256

// ---------- persistent transposed weights (device globals, no allocs) ----------
__device__ float g_Wru[264 * 400];   // [K=264][400] fused r,u over [x;h]
__device__ float g_bru[400];
__device__ float g_Win[64 * 200];    // i_n over x
__device__ float g_bin[200];
__device__ float g_Whn[200 * 200];   // h_n over h
__device__ float g_bhn[200];
__device__ float g_W1t[200 * 200];
__device__ float g_b1s[200];
__device__ float g_W2t[200 * 200];
__device__ float g_b2s[200];
__device__ float g_Wms[200 * 64];    // heads: cols 0..31 mean, 32..63 logstd
__device__ float g_bms[64];

// ---------- packed fp32x2 helpers ----------
__device__ __forceinline__ unsigned long long fma2_(unsigned long long a,
                                                    unsigned long long b,
                                                    unsigned long long c) {
    unsigned long long d;
    asm("fma.rn.f32x2 %0, %1, %2, %3;" : "=l"(d) : "l"(a), "l"(b), "l"(c));
    return d;
}
__device__ __forceinline__ unsigned long long splat2_(float w) {
    unsigned long long d;
    asm("mov.b64 %0, {%1, %1};" : "=l"(d) : "f"(w));
    return d;
}
__device__ __forceinline__ void unpack2_(unsigned long long v, float& lo, float& hi) {
    asm("mov.b64 {%0, %1}, %2;" : "=f"(lo), "=f"(hi) : "l"(v));
}

// ---------- weight transpose / fuse (runs every launch; deterministic) ----------
__global__ void rssm_preproc(
    const float* __restrict__ W_ih, const float* __restrict__ b_ih,
    const float* __restrict__ W_hh, const float* __restrict__ b_hh,
    const float* __restrict__ W1,   const float* __restrict__ b1,
    const float* __restrict__ W2,   const float* __restrict__ b2,
    const float* __restrict__ Wm,   const float* __restrict__ bm,
    const float* __restrict__ Ws,   const float* __restrict__ bs)
{
    int i0 = blockIdx.x * blockDim.x + threadIdx.x;
    int stride = gridDim.x * blockDim.x;

    for (int idx = i0; idx < 264 * 400; idx += stride) {
        int k = idx / 400, o = idx % 400;
        g_Wru[idx] = (k < 64) ? W_ih[o * 64 + k] : W_hh[o * 200 + (k - 64)];
    }
    for (int idx = i0; idx < 400; idx += stride) g_bru[idx] = b_ih[idx] + b_hh[idx];

    for (int idx = i0; idx < 64 * 200; idx += stride) {
        int k = idx / 200, o = idx % 200;
        g_Win[idx] = W_ih[(400 + o) * 64 + k];
    }
    for (int idx = i0; idx < 200; idx += stride) g_bin[idx] = b_ih[400 + idx];

    for (int idx = i0; idx < 200 * 200; idx += stride) {
        int k = idx / 200, o = idx % 200;
        g_Whn[idx] = W_hh[(400 + o) * 200 + k];
        g_W1t[idx] = W1[o * 200 + k];
        g_W2t[idx] = W2[o * 200 + k];
    }
    for (int idx = i0; idx < 200; idx += stride) {
        g_bhn[idx] = b_hh[400 + idx];
        g_b1s[idx] = b1[idx];
        g_b2s[idx] = b2[idx];
    }

    for (int idx = i0; idx < 200 * 64; idx += stride) {
        int k = idx / 64, o = idx % 64;
        g_Wms[idx] = (o < 32) ? Wm[o * 200 + k] : Ws[(o - 32) * 200 + k];
    }
    for (int idx = i0; idx < 64; idx += stride)
        g_bms[idx] = (idx < 32) ? bm[idx] : bs[idx - 32];
}

// ---------- register-tiled GEMM: outT[NOUT][16] = Wt[K][NOUT]*inT[K][16]+bias
// Thread tile: C cols x (16/RG) rows. ACT: 0=none, 1=sigmoid, 2=elu.
template<int K, int NOUT, int C, int RG, int ACT>
__device__ __forceinline__ void gemm_rc(const float* __restrict__ Wt,
                                        const float* __restrict__ bias,
                                        const float* __restrict__ inT,
                                        float* __restrict__ outT, int tid)
{
    constexpr int NCG = NOUT / C;   // column groups
    constexpr int RPT = BT / RG;    // rows per thread
    constexpr int NU  = RPT / 2;    // u64 accumulators per column

    if (tid < NCG * RG) {
        const int cg = tid / RG;
        const int rg = tid - cg * RG;
        const float* wp = Wt + cg * C;
        const float* xb = inT + rg * RPT;

        unsigned long long acc[C][NU];
#pragma unroll
        for (int ci = 0; ci < C; ci++)
#pragma unroll
            for (int q = 0; q < NU; q++) acc[ci][q] = 0ull;

#pragma unroll 4
        for (int k = 0; k < K; k++) {
            float w[C];
            if (C == 4) {
                float4 t = __ldg(reinterpret_cast<const float4*>(wp + (size_t)k * NOUT));
                w[0] = t.x; w[1] = t.y; w[2] = t.z; w[3] = t.w;
            } else {
                float2 t = __ldg(reinterpret_cast<const float2*>(wp + (size_t)k * NOUT));
                w[0] = t.x; w[1] = t.y;
            }
            unsigned long long xv[NU];
            const ulonglong2* xp = reinterpret_cast<const ulonglong2*>(xb + k * BT);
#pragma unroll
            for (int h = 0; h < NU / 2; h++) {
                ulonglong2 t = xp[h];
                xv[2 * h] = t.x; xv[2 * h + 1] = t.y;
            }
#pragma unroll
            for (int ci = 0; ci < C; ci++) {
                unsigned long long wd = splat2_(w[ci]);
#pragma unroll
                for (int q = 0; q < NU; q++) acc[ci][q] = fma2_(wd, xv[q], acc[ci][q]);
            }
        }

#pragma unroll
        for (int ci = 0; ci < C; ci++) {
            int c = cg * C + ci;
            float bv = bias[c];
            float v[RPT];
#pragma unroll
            for (int q = 0; q < NU; q++) {
                unpack2_(acc[ci][q], v[2 * q], v[2 * q + 1]);
                v[2 * q] += bv; v[2 * q + 1] += bv;
            }
            if (ACT == 1) {
#pragma unroll
                for (int r = 0; r < RPT; r++) v[r] = 1.0f / (1.0f + __expf(-v[r]));
            } else if (ACT == 2) {
#pragma unroll
                for (int r = 0; r < RPT; r++) v[r] = v[r] > 0.0f ? v[r] : (__expf(v[r]) - 1.0f);
            }
            float4* op = reinterpret_cast<float4*>(outT + c * BT + rg * RPT);
#pragma unroll
            for (int h = 0; h < RPT / 4; h++)
                op[h] = make_float4(v[4 * h], v[4 * h + 1], v[4 * h + 2], v[4 * h + 3]);
        }
    }
}

// ---------- main rollout kernel: 1 CTA = 16 batch rows, all 64 steps ----------
extern __shared__ float smf[];

// SMEM float offsets
#define OXH  0       // [264][16]: rows 0..31 z, 32..63 a, 64..263 h
#define OEP  4224    // [32][16] eps
#define ORU  4736    // [400][16] sigmoid(r,u); aliased by head partials
#define OHP  4736    // [4][64][16] head partials
#define OMS  8832    // [64][16] mean(0..31), std(32..63)
#define ONB1 11136   // [200][16]
#define ONB2 14336   // [200][16]
#define SMEMB (17536 * 4)

__global__ void __launch_bounds__(NT, 1) rssm_main(
    const float* __restrict__ h0, const float* __restrict__ z0,
    const float* __restrict__ actions, const float* __restrict__ eps,
    float* __restrict__ out)
{
    float* xh  = smf + OXH;
    float* ep  = smf + OEP;
    float* ru  = smf + ORU;
    float* hp  = smf + OHP;
    float* ms  = smf + OMS;
    float* nb1 = smf + ONB1;
    float* nb2 = smf + ONB2;

    const int tid = threadIdx.x;
    const int b0  = blockIdx.x * BT;

    // initial state (h0, z0), feature-major
    for (int idx = tid; idx < Dn * BT; idx += NT) {
        int f = idx >> 4, r = idx & 15;
        xh[64 * BT + idx] = h0[(b0 + r) * Dn + f];
    }
    for (int idx = tid; idx < Sn * BT; idx += NT) {
        int f = idx >> 4, r = idx & 15;
        xh[idx] = z0[(b0 + r) * Sn + f];
    }

    for (int t = 0; t < Hn; t++) {
        // stage actions[t], eps[t]
        for (int idx = tid; idx < An * BT; idx += NT) {
            int r = idx >> 5, c = idx & 31;
            size_t gbase = ((size_t)(b0 + r) * Hn + t);
            xh[(32 + c) * BT + r] = actions[gbase * An + c];
            ep[c * BT + r]        = eps[gbase * Sn + c];
        }
        __syncthreads();

        // gate GEMMs (independent; no syncs between)
        gemm_rc<264, 400, 4, 2, 1>(g_Wru, g_bru, xh, ru, tid);            // sigmoid(r,u)
        gemm_rc< 64, 200, 4, 4, 0>(g_Win, g_bin, xh, nb1, tid);           // i_n
        gemm_rc<200, 200, 4, 4, 0>(g_Whn, g_bhn, xh + 64 * BT, nb2, tid); // h_n
        __syncthreads();

        // pointwise GRU update (in place on h region)
        for (int idx = tid; idx < Dn * BT; idx += NT) {
            float rr = ru[idx], u = ru[3200 + idx];
            float n  = tanhf(nb1[idx] + rr * nb2[idx]);
            float hv = xh[64 * BT + idx];
            xh[64 * BT + idx] = (1.0f - u) * n + u * hv;
        }
        __syncthreads();

        gemm_rc<200, 200, 4, 4, 2>(g_W1t, g_b1s, xh + 64 * BT, nb1, tid); // f1
        __syncthreads();
        gemm_rc<200, 200, 4, 4, 2>(g_W2t, g_b2s, nb1, nb2, tid);          // f2
        __syncthreads();

        // heads (Nout=64, K=200), 4-way K-split: o = tid&63, part p = tid>>6
        {
            int o = tid & 63, p = tid >> 6;
            const float* wp = g_Wms + p * 50 * 64 + o;
            const float* xb = nb2 + p * 50 * BT;
            unsigned long long acc[8];
#pragma unroll
            for (int q = 0; q < 8; q++) acc[q] = 0ull;
#pragma unroll 5
            for (int k = 0; k < 50; k += 2) {
                float w0 = __ldg(wp + k * 64);
                float w1 = __ldg(wp + (k + 1) * 64);
                unsigned long long wd0 = splat2_(w0), wd1 = splat2_(w1);
                const ulonglong2* x0 = reinterpret_cast<const ulonglong2*>(xb + k * BT);
                const ulonglong2* x1 = reinterpret_cast<const ulonglong2*>(xb + (k + 1) * BT);
#pragma unroll
                for (int q = 0; q < 4; q++) {
                    ulonglong2 a = x0[q], b = x1[q];
                    acc[2 * q]     = fma2_(wd0, a.x, acc[2 * q]);
                    acc[2 * q + 1] = fma2_(wd0, a.y, acc[2 * q + 1]);
                    acc[2 * q]     = fma2_(wd1, b.x, acc[2 * q]);
                    acc[2 * q + 1] = fma2_(wd1, b.y, acc[2 * q + 1]);
                }
            }
            float v[16];
#pragma unroll
            for (int q = 0; q < 8; q++) { unpack2_(acc[q], v[2 * q], v[2 * q + 1]); }
            float4* dp = reinterpret_cast<float4*>(hp + p * 1024 + o * BT);
#pragma unroll
            for (int q = 0; q < 4; q++)
                dp[q] = make_float4(v[4 * q], v[4 * q + 1], v[4 * q + 2], v[4 * q + 3]);
        }
        __syncthreads();

        // reduce K-split partials; mean raw, std = exp(clip(logstd))
        for (int idx = tid; idx < 1024; idx += NT) {
            int o = idx >> 4;
            float v = hp[idx] + hp[1024 + idx] + hp[2048 + idx] + hp[3072 + idx] + g_bms[o];
            if (o < 32) ms[idx] = v;
            else        ms[idx] = __expf(fminf(fmaxf(v, -10.0f), 2.0f));
        }
        __syncthreads();

        // z_new = mean + std*eps (state for next step)
        for (int idx = tid; idx < Sn * BT; idx += NT)
            xh[idx] = ms[idx] + ms[512 + idx] * ep[idx];

        // emit outputs: [h(200) | z(32) | mean(32) | std(32)]
        for (int idx = tid; idx < OUTC * BT; idx += NT) {
            int r = idx / OUTC, c = idx - r * OUTC;
            float v;
            if (c < 200)       v = xh[64 * BT + c * BT + r];
            else if (c < 232) { int s = c - 200; v = ms[s * BT + r] + ms[(32 + s) * BT + r] * ep[s * BT + r]; }
            else               v = ms[(c - 232) * BT + r];
            out[((size_t)(b0 + r) * Hn + t) * OUTC + c] = v;
        }
        __syncthreads();
    }
}

// ---------- launch ----------
extern "C" void kernel_launch(void* const* d_in, const int* in_sizes, int n_in,
                              void* d_out, int out_size)
{
    const float* h0      = (const float*)d_in[0];
    const float* z0      = (const float*)d_in[1];
    const float* actions = (const float*)d_in[2];
    const float* eps_    = (const float*)d_in[3];
    const float* W_ih = (const float*)d_in[4];  const float* b_ih = (const float*)d_in[5];
    const float* W_hh = (const float*)d_in[6];  const float* b_hh = (const float*)d_in[7];
    const float* W1   = (const float*)d_in[8];  const float* b1   = (const float*)d_in[9];
    const float* W2   = (const float*)d_in[10]; const float* b2   = (const float*)d_in[11];
    const float* Wm   = (const float*)d_in[12]; const float* bm   = (const float*)d_in[13];
    const float* Ws   = (const float*)d_in[14]; const float* bs   = (const float*)d_in[15];
    float* out = (float*)d_out;

    cudaFuncSetAttribute(rssm_main, cudaFuncAttributeMaxDynamicSharedMemorySize, SMEMB);

    rssm_preproc<<<128, 256>>>(W_ih, b_ih, W_hh, b_hh, W1, b1, W2, b2, Wm, bm, Ws, bs);
    rssm_main<<<Bn / BT, NT, SMEMB>>>(h0, z0, actions, eps_, out);
}

// round 4
// speedup vs baseline: 1.6085x; 1.6085x over previous
#include <cuda_runtime.h>
#include <math.h>

#define Bn   2048
#define Hn   64
#define An   32
#define Sn   32
#define Dn   200
#define OUTC 296
#define BT   16
#define NT   256

// padded K sizes (multiples of 16)
#define KXH  272   // [z|a|h] = 264 -> 272
#define KH   208   // 200 -> 208

// ---------- persistent transposed weights (device globals, zero-padded K rows) ----------
__device__ float g_Wru[KXH * 400];
__device__ float g_bru[400];
__device__ float g_Win[64 * 200];
__device__ float g_bin[200];
__device__ float g_Whn[KH * 200];
__device__ float g_bhn[200];
__device__ float g_W1t[KH * 200];
__device__ float g_b1s[200];
__device__ float g_W2t[KH * 200];
__device__ float g_b2s[200];
__device__ float g_Wms[KH * 64];
__device__ float g_bms[64];

// ---------- packed fp32x2 helpers ----------
__device__ __forceinline__ unsigned long long fma2_(unsigned long long a,
                                                    unsigned long long b,
                                                    unsigned long long c) {
    unsigned long long d;
    asm("fma.rn.f32x2 %0, %1, %2, %3;" : "=l"(d) : "l"(a), "l"(b), "l"(c));
    return d;
}
__device__ __forceinline__ unsigned long long splat2_(float w) {
    unsigned long long d;
    asm("mov.b64 %0, {%1, %1};" : "=l"(d) : "f"(w));
    return d;
}
__device__ __forceinline__ void unpack2_(unsigned long long v, float& lo, float& hi) {
    asm("mov.b64 {%0, %1}, %2;" : "=f"(lo), "=f"(hi) : "l"(v));
}

// ---------- weight transpose / fuse ----------
__global__ void rssm_preproc(
    const float* __restrict__ W_ih, const float* __restrict__ b_ih,
    const float* __restrict__ W_hh, const float* __restrict__ b_hh,
    const float* __restrict__ W1,   const float* __restrict__ b1,
    const float* __restrict__ W2,   const float* __restrict__ b2,
    const float* __restrict__ Wm,   const float* __restrict__ bm,
    const float* __restrict__ Ws,   const float* __restrict__ bs)
{
    int i0 = blockIdx.x * blockDim.x + threadIdx.x;
    int stride = gridDim.x * blockDim.x;

    for (int idx = i0; idx < KXH * 400; idx += stride) {
        int k = idx / 400, o = idx % 400;
        float v = 0.0f;
        if (k < 64) v = W_ih[o * 64 + k];
        else if (k < 264) v = W_hh[o * 200 + (k - 64)];
        g_Wru[idx] = v;
    }
    for (int idx = i0; idx < 400; idx += stride) g_bru[idx] = b_ih[idx] + b_hh[idx];

    for (int idx = i0; idx < 64 * 200; idx += stride) {
        int k = idx / 200, o = idx % 200;
        g_Win[idx] = W_ih[(400 + o) * 64 + k];
    }
    for (int idx = i0; idx < 200; idx += stride) g_bin[idx] = b_ih[400 + idx];

    for (int idx = i0; idx < KH * 200; idx += stride) {
        int k = idx / 200, o = idx % 200;
        bool live = (k < 200);
        g_Whn[idx] = live ? W_hh[(400 + o) * 200 + k] : 0.0f;
        g_W1t[idx] = live ? W1[o * 200 + k] : 0.0f;
        g_W2t[idx] = live ? W2[o * 200 + k] : 0.0f;
    }
    for (int idx = i0; idx < 200; idx += stride) {
        g_bhn[idx] = b_hh[400 + idx];
        g_b1s[idx] = b1[idx];
        g_b2s[idx] = b2[idx];
    }

    for (int idx = i0; idx < KH * 64; idx += stride) {
        int k = idx / 64, o = idx % 64;
        float v = 0.0f;
        if (k < 200) v = (o < 32) ? Wm[o * 200 + k] : Ws[(o - 32) * 200 + k];
        g_Wms[idx] = v;
    }
    for (int idx = i0; idx < 64; idx += stride)
        g_bms[idx] = (idx < 32) ? bm[idx] : bs[idx - 32];
}

// ---------- register-tiled GEMM with 8-deep double-buffered weight prefetch ----
// outT[NOUT][16] = Wt[K][NOUT] * inT[K][16] + bias. Thread tile: 4 cols x (16/RG) rows.
// K must be a multiple of 16. ACT: 0=none, 1=sigmoid, 2=elu.
template<int K, int NOUT, int RG, int ACT>
__device__ __forceinline__ void gemm_rc(const float* __restrict__ Wt,
                                        const float* __restrict__ bias,
                                        const float* __restrict__ inT,
                                        float* __restrict__ outT, int tid)
{
    constexpr int C   = 4;
    constexpr int NCG = NOUT / C;
    constexpr int RPT = BT / RG;
    constexpr int NU  = RPT / 2;
    static_assert(K % 16 == 0, "K pad");

    if (tid < NCG * RG) {
        const int cg = tid / RG;
        const int rg = tid - cg * RG;
        const float* wp = Wt + cg * C;
        const float* xb = inT + rg * RPT;

        unsigned long long acc[C][NU];
#pragma unroll
        for (int ci = 0; ci < C; ci++)
#pragma unroll
            for (int q = 0; q < NU; q++) acc[ci][q] = 0ull;

        auto LD = [&](float4* buf, int k0) {
#pragma unroll
            for (int p = 0; p < 8; p++)
                buf[p] = __ldg(reinterpret_cast<const float4*>(wp + (size_t)(k0 + p) * NOUT));
        };
        auto CP = [&](const float4* buf, int k0) {
#pragma unroll
            for (int p = 0; p < 8; p++) {
                int k = k0 + p;
                unsigned long long xv[NU];
                const ulonglong2* xp = reinterpret_cast<const ulonglong2*>(xb + k * BT);
#pragma unroll
                for (int h = 0; h < NU / 2; h++) {
                    ulonglong2 t = xp[h];
                    xv[2 * h] = t.x; xv[2 * h + 1] = t.y;
                }
                float w[4] = {buf[p].x, buf[p].y, buf[p].z, buf[p].w};
#pragma unroll
                for (int ci = 0; ci < C; ci++) {
                    unsigned long long wd = splat2_(w[ci]);
#pragma unroll
                    for (int q = 0; q < NU; q++) acc[ci][q] = fma2_(wd, xv[q], acc[ci][q]);
                }
            }
        };

        float4 bufA[8], bufB[8];
        LD(bufA, 0);
        for (int k0 = 0; k0 < K; k0 += 16) {
            LD(bufB, k0 + 8);
            CP(bufA, k0);
            if (k0 + 16 < K) LD(bufA, k0 + 16);
            CP(bufB, k0 + 8);
        }

#pragma unroll
        for (int ci = 0; ci < C; ci++) {
            int c = cg * C + ci;
            float bv = bias[c];
            float v[RPT];
#pragma unroll
            for (int q = 0; q < NU; q++) {
                unpack2_(acc[ci][q], v[2 * q], v[2 * q + 1]);
                v[2 * q] += bv; v[2 * q + 1] += bv;
            }
            if (ACT == 1) {
#pragma unroll
                for (int r = 0; r < RPT; r++) v[r] = 1.0f / (1.0f + __expf(-v[r]));
            } else if (ACT == 2) {
#pragma unroll
                for (int r = 0; r < RPT; r++) v[r] = v[r] > 0.0f ? v[r] : (__expf(v[r]) - 1.0f);
            }
            float4* op = reinterpret_cast<float4*>(outT + c * BT + rg * RPT);
#pragma unroll
            for (int h = 0; h < RPT / 4; h++)
                op[h] = make_float4(v[4 * h], v[4 * h + 1], v[4 * h + 2], v[4 * h + 3]);
        }
    }
}

// ---------- main rollout kernel: 1 CTA = 16 batch rows, all 64 steps ----------
extern __shared__ float smf[];

// SMEM float offsets (padded)
#define OXH  0               // [272][16]: z 0..31, a 32..63, h 64..263, pad 264..271
#define OEP  (272*16)        // [32][16]
#define ORU  (OEP + 32*16)   // [400][16]; aliased by head partials
#define OHP  ORU             // [4][64][16]
#define OMS  (ORU + 400*16)  // [64][16] mean(0..31), std(32..63)
#define ONB1 (OMS + 64*16)   // [208][16]
#define ONB2 (ONB1 + 208*16) // [208][16]
#define SMEMF (ONB2 + 208*16)
#define SMEMB (SMEMF * 4)

__global__ void __launch_bounds__(NT, 1) rssm_main(
    const float* __restrict__ h0, const float* __restrict__ z0,
    const float* __restrict__ actions, const float* __restrict__ eps,
    float* __restrict__ out)
{
    float* xh  = smf + OXH;
    float* ep  = smf + OEP;
    float* ru  = smf + ORU;
    float* hp  = smf + OHP;
    float* ms  = smf + OMS;
    float* nb1 = smf + ONB1;
    float* nb2 = smf + ONB2;

    const int tid = threadIdx.x;
    const int b0  = blockIdx.x * BT;

    // initial state + zero the K-padding rows (outputs never touch them)
    for (int idx = tid; idx < Dn * BT; idx += NT) {
        int f = idx >> 4, r = idx & 15;
        xh[64 * BT + idx] = h0[(b0 + r) * Dn + f];
    }
    for (int idx = tid; idx < Sn * BT; idx += NT) {
        int f = idx >> 4, r = idx & 15;
        xh[idx] = z0[(b0 + r) * Sn + f];
    }
    for (int idx = tid; idx < 8 * BT; idx += NT) {
        xh[264 * BT + idx] = 0.0f;
        nb1[200 * BT + idx] = 0.0f;
        nb2[200 * BT + idx] = 0.0f;
    }

    for (int t = 0; t < Hn; t++) {
        // stage actions[t], eps[t]
        for (int idx = tid; idx < An * BT; idx += NT) {
            int r = idx >> 5, c = idx & 31;
            size_t gbase = ((size_t)(b0 + r) * Hn + t);
            xh[(32 + c) * BT + r] = actions[gbase * An + c];
            ep[c * BT + r]        = eps[gbase * Sn + c];
        }
        __syncthreads();

        // gate GEMMs (independent)
        gemm_rc<KXH, 400, 2, 1>(g_Wru, g_bru, xh, ru, tid);            // sigmoid(r,u)
        gemm_rc< 64, 200, 4, 0>(g_Win, g_bin, xh, nb1, tid);           // i_n
        gemm_rc< KH, 200, 4, 0>(g_Whn, g_bhn, xh + 64 * BT, nb2, tid); // h_n
        __syncthreads();

        // pointwise GRU update (in place on h region)
        for (int idx = tid; idx < Dn * BT; idx += NT) {
            float rr = ru[idx], u = ru[3200 + idx];
            float n  = tanhf(nb1[idx] + rr * nb2[idx]);
            float hv = xh[64 * BT + idx];
            xh[64 * BT + idx] = (1.0f - u) * n + u * hv;
        }
        __syncthreads();

        gemm_rc<KH, 200, 4, 2>(g_W1t, g_b1s, xh + 64 * BT, nb1, tid);  // f1
        __syncthreads();
        gemm_rc<KH, 200, 4, 2>(g_W2t, g_b2s, nb1, nb2, tid);           // f2
        __syncthreads();

        // heads (Nout=64, padded K=208), 4-way K-split of 52
        {
            int o = tid & 63, p = tid >> 6;
            const float* wp = g_Wms + p * 52 * 64 + o;
            const float* xb = nb2 + p * 52 * BT;
            unsigned long long acc[8];
#pragma unroll
            for (int q = 0; q < 8; q++) acc[q] = 0ull;
#pragma unroll 4
            for (int k = 0; k < 52; k += 2) {
                float w0 = __ldg(wp + k * 64);
                float w1 = __ldg(wp + (k + 1) * 64);
                unsigned long long wd0 = splat2_(w0), wd1 = splat2_(w1);
                const ulonglong2* x0 = reinterpret_cast<const ulonglong2*>(xb + k * BT);
                const ulonglong2* x1 = reinterpret_cast<const ulonglong2*>(xb + (k + 1) * BT);
#pragma unroll
                for (int q = 0; q < 4; q++) {
                    ulonglong2 a = x0[q], b = x1[q];
                    acc[2 * q]     = fma2_(wd0, a.x, acc[2 * q]);
                    acc[2 * q + 1] = fma2_(wd0, a.y, acc[2 * q + 1]);
                    acc[2 * q]     = fma2_(wd1, b.x, acc[2 * q]);
                    acc[2 * q + 1] = fma2_(wd1, b.y, acc[2 * q + 1]);
                }
            }
            float v[16];
#pragma unroll
            for (int q = 0; q < 8; q++) { unpack2_(acc[q], v[2 * q], v[2 * q + 1]); }
            float4* dp = reinterpret_cast<float4*>(hp + p * 1024 + o * BT);
#pragma unroll
            for (int q = 0; q < 4; q++)
                dp[q] = make_float4(v[4 * q], v[4 * q + 1], v[4 * q + 2], v[4 * q + 3]);
        }
        __syncthreads();

        // reduce K-split partials; mean raw, std = exp(clip(logstd))
        for (int idx = tid; idx < 1024; idx += NT) {
            int o = idx >> 4;
            float v = hp[idx] + hp[1024 + idx] + hp[2048 + idx] + hp[3072 + idx] + g_bms[o];
            if (o < 32) ms[idx] = v;
            else        ms[idx] = __expf(fminf(fmaxf(v, -10.0f), 2.0f));
        }
        __syncthreads();

        // z_new = mean + std*eps (state for next step)
        for (int idx = tid; idx < Sn * BT; idx += NT)
            xh[idx] = ms[idx] + ms[512 + idx] * ep[idx];

        // emit outputs: [h(200) | z(32) | mean(32) | std(32)]
        for (int idx = tid; idx < OUTC * BT; idx += NT) {
            int r = idx / OUTC, c = idx - r * OUTC;
            float v;
            if (c < 200)       v = xh[64 * BT + c * BT + r];
            else if (c < 232) { int s = c - 200; v = ms[s * BT + r] + ms[(32 + s) * BT + r] * ep[s * BT + r]; }
            else               v = ms[(c - 232) * BT + r];
            out[((size_t)(b0 + r) * Hn + t) * OUTC + c] = v;
        }
        __syncthreads();
    }
}

// ---------- launch ----------
extern "C" void kernel_launch(void* const* d_in, const int* in_sizes, int n_in,
                              void* d_out, int out_size)
{
    const float* h0      = (const float*)d_in[0];
    const float* z0      = (const float*)d_in[1];
    const float* actions = (const float*)d_in[2];
    const float* eps_    = (const float*)d_in[3];
    const float* W_ih = (const float*)d_in[4];  const float* b_ih = (const float*)d_in[5];
    const float* W_hh = (const float*)d_in[6];  const float* b_hh = (const float*)d_in[7];
    const float* W1   = (const float*)d_in[8];  const float* b1   = (const float*)d_in[9];
    const float* W2   = (const float*)d_in[10]; const float* b2   = (const float*)d_in[11];
    const float* Wm   = (const float*)d_in[12]; const float* bm   = (const float*)d_in[13];
    const float* Ws   = (const float*)d_in[14]; const float* bs   = (const float*)d_in[15];
    float* out = (float*)d_out;

    cudaFuncSetAttribute(rssm_main, cudaFuncAttributeMaxDynamicSharedMemorySize, SMEMB);

    rssm_preproc<<<128, 256>>>(W_ih, b_ih, W_hh, b_hh, W1, b1, W2, b2, Wm, bm, Ws, bs);
    rssm_main<<<Bn / BT, NT, SMEMB>>>(h0, z0, actions, eps_, out);
}